// round 4
// baseline (speedup 1.0000x reference)
#include <cuda_runtime.h>
#include <math.h>

typedef unsigned long long ull;

#define TRAJ 3
#define BATCH 2048
#define NROW (TRAJ*BATCH)     // 6144
#define LAT 123
#define DIMA 128
#define HID 256
#define NT 50
#define NSTEP (NT-1)          // 49

#define MROW 48               // rows per block (6144 = 128 * 48, exact)
#define NPAIR (MROW/2)        // 24 row-pairs (phase 1 accumulators)
#define HPAIR 12              // row-pairs per phase-2 thread (half of 24)
#define NBLK (NROW/MROW)      // 128 blocks -> single wave on 148 SMs
#define NTHR 256

#define YS 52                 // yin row stride (floats); 52 mod 32 = 20 -> 4-way max on scalar writes, 16B aligned
#define AS 52                 // act row stride (floats)
#define W1T_FLOATS (DIMA*HID)               // 32768
#define YIN_OFF  W1T_FLOATS
#define ACT_OFF  (W1T_FLOATS + DIMA*YS)
#define SMEM_FLOATS (W1T_FLOATS + DIMA*YS + HID*AS)   // 52736 floats
#define SMEM_BYTES (SMEM_FLOATS*4)                    // 210944 B <= 227KB

// ---- packed f32x2 helpers (Blackwell dual-rate fp32 path, PTX-only) ----
__device__ __forceinline__ ull pk2(float lo, float hi){
  ull r; asm("mov.b64 %0, {%1, %2};" : "=l"(r) : "f"(lo), "f"(hi)); return r;
}
__device__ __forceinline__ void upk2(ull v, float &lo, float &hi){
  asm("mov.b64 {%0, %1}, %2;" : "=f"(lo), "=f"(hi) : "l"(v));
}
__device__ __forceinline__ ull fma2_(ull a, ull b, ull c){
  ull d; asm("fma.rn.f32x2 %0, %1, %2, %3;" : "=l"(d) : "l"(a), "l"(b), "l"(c)); return d;
}
__device__ __forceinline__ ull add2_(ull a, ull b){
  ull d; asm("add.rn.f32x2 %0, %1, %2;" : "=l"(d) : "l"(a), "l"(b)); return d;
}

// tanh via exp: |err| ~1e-6, 2 MUFU ops. Safe for rel_err 1e-3 budget.
__device__ __forceinline__ float fast_tanh(float x){
  float ax = fabsf(x);
  float e = __expf(-2.0f * ax);            // in (0,1], no overflow
  float r = __fdividef(1.0f - e, 1.0f + e);
  return copysignf(r, x);
}

__global__ __launch_bounds__(NTHR, 1)
void ode_rk4_kernel(const float* __restrict__ fp, const float* __restrict__ ts,
                    const float* __restrict__ W1, const float* __restrict__ b1,
                    const float* __restrict__ W2, const float* __restrict__ b2,
                    float* __restrict__ out)
{
  extern __shared__ float sm[];
  float* w1t = sm;                 // W1 transposed: [d=128][j=256], stride 256
  float* yin = sm + YIN_OFF;       // stage input:   [d=128][r=48],  stride YS
  float* act = sm + ACT_OFF;       // activations:   [j=256][r=48],  stride AS

  const int tid  = threadIdx.x;
  const int dd   = tid & (DIMA-1);   // phase-2 output dim
  const int rh   = tid >> 7;         // phase-2 row half (0/1)
  const int rb   = rh * NPAIR;       // 0 or 24
  const int row0 = blockIdx.x * MROW;

  // ---- stage W1 transposed into smem (one-time) ----
  for (int idx = tid; idx < HID*DIMA; idx += NTHR){
    int j = idx >> 7;              // hidden row of W1
    int d = idx & (DIMA-1);
    w1t[d*HID + j] = W1[idx];
  }

  // ---- init state: y0 = [first_point | zeros(AUG)] ; write t=0 output ----
  ull y2[HPAIR], k1p[HPAIR], k2p[HPAIR], k3p[HPAIR];
  #pragma unroll
  for (int i=0;i<HPAIR;i++){
    int r0 = rb + 2*i;
    int g0 = row0 + r0;
    float v0 = (dd < LAT) ? __ldg(fp + (size_t)g0*LAT + dd) : 0.0f;
    float v1 = (dd < LAT) ? __ldg(fp + (size_t)(g0+1)*LAT + dd) : 0.0f;
    y2[i] = pk2(v0, v1);
    *(ull*)(yin + dd*YS + r0) = y2[i];
    out[((size_t)g0*NT)*DIMA + dd]     = v0;
    out[((size_t)(g0+1)*NT)*DIMA + dd] = v1;
  }

  const float bj  = __ldg(b1 + tid);
  const float bd  = __ldg(b2 + dd);
  const ull   bdp = pk2(bd, bd);
  const float4* w2p = (const float4*)(W2 + (size_t)dd*HID);
  const float* w1col = w1t + tid;

  __syncthreads();

  for (int step = 0; step < NSTEP; ++step){
    const float t0 = __ldg(ts + step);
    const float t1 = __ldg(ts + step + 1);
    const float h  = t1 - t0;

    for (int st = 0; st < 4; ++st){
      // ============ phase 1: act = tanh(yin @ W1^T + b1) ============
      // thread tid owns hidden unit j = tid, all 48 rows (24 f32x2 pairs)
      {
        ull acc[NPAIR];
        #pragma unroll
        for (int i=0;i<NPAIR;i++) acc[i] = 0ull;
        #pragma unroll 4
        for (int d=0; d<DIMA; ++d){
          float w = w1col[d*HID];                       // lane-stride-1: conflict-free
          ull wp = pk2(w, w);
          const ulonglong2* yp = (const ulonglong2*)(yin + d*YS);   // broadcast
          #pragma unroll
          for (int i=0;i<HPAIR;i++){
            ulonglong2 v = yp[i];
            acc[2*i]   = fma2_(wp, v.x, acc[2*i]);
            acc[2*i+1] = fma2_(wp, v.y, acc[2*i+1]);
          }
        }
        float* arow = act + tid*AS;
        #pragma unroll
        for (int p=0;p<NPAIR;p++){
          float lo, hi; upk2(acc[p], lo, hi);
          lo = fast_tanh(lo + bj);
          hi = fast_tanh(hi + bj);
          *(ull*)(arow + 2*p) = pk2(lo, hi);
        }
      }
      __syncthreads();

      // ============ phase 2: k = act @ W2^T + b2 ============
      // thread (dd, rh) owns output dim dd for rows [rb, rb+24)
      ull kv[HPAIR];
      {
        ull a2[HPAIR];
        #pragma unroll
        for (int i=0;i<HPAIR;i++) a2[i] = 0ull;
        float4 wv = __ldg(w2p);                          // prefetch first weight vec
        #pragma unroll 2
        for (int h4=0; h4<HID/4; ++h4){
          float4 cw = wv;
          if (h4+1 < HID/4) wv = __ldg(w2p + h4 + 1);    // rolling prefetch from L1/L2
          const float* ab = act + (4*h4)*AS + rb;
          float ws[4] = {cw.x, cw.y, cw.z, cw.w};
          #pragma unroll
          for (int s=0;s<4;s++){
            ull wp = pk2(ws[s], ws[s]);
            const ulonglong2* ap = (const ulonglong2*)(ab + s*AS);  // broadcast, 16B aligned
            #pragma unroll
            for (int i=0;i<HPAIR/2;i++){
              ulonglong2 v = ap[i];
              a2[2*i]   = fma2_(wp, v.x, a2[2*i]);
              a2[2*i+1] = fma2_(wp, v.y, a2[2*i+1]);
            }
          }
        }
        #pragma unroll
        for (int i=0;i<HPAIR;i++) kv[i] = add2_(a2[i], bdp);
      }

      // ============ RK4(3/8) stage update (packed, register-resident k's) ====
      ull* ybase = (ull*)(yin + dd*YS + rb);
      if (st == 0){
        const float c = h*(1.0f/3.0f);
        const ull H3 = pk2(c, c);
        #pragma unroll
        for (int i=0;i<HPAIR;i++){
          k1p[i] = kv[i];
          ybase[i] = fma2_(H3, kv[i], y2[i]);            // y + h*k1/3
        }
      } else if (st == 1){
        const ull Hp  = pk2(h, h);
        const float c = -h*(1.0f/3.0f);
        const ull nH3 = pk2(c, c);
        #pragma unroll
        for (int i=0;i<HPAIR;i++){
          k2p[i] = kv[i];
          ull t = fma2_(Hp, kv[i], y2[i]);               // y + h*k2
          ybase[i] = fma2_(nH3, k1p[i], t);              //   - h*k1/3
        }
      } else if (st == 2){
        const ull Hp = pk2(h, h);
        const ull N1 = pk2(-1.0f, -1.0f);
        #pragma unroll
        for (int i=0;i<HPAIR;i++){
          k3p[i] = kv[i];
          ull t = fma2_(N1, k2p[i], k1p[i]);             // k1 - k2
          t = add2_(t, kv[i]);                           //   + k3
          ybase[i] = fma2_(Hp, t, y2[i]);                // y + h*(...)
        }
      } else {
        const ull TH = pk2(3.0f, 3.0f);
        const float c = h*0.125f;
        const ull H8 = pk2(c, c);
        #pragma unroll
        for (int i=0;i<HPAIR;i++){
          ull t = add2_(k1p[i], kv[i]);                  // k1 + k4
          ull u = add2_(k2p[i], k3p[i]);                 // k2 + k3
          t = fma2_(TH, u, t);                           // k1 + 3k2 + 3k3 + k4
          ull yn = fma2_(H8, t, y2[i]);                  // y + h*sum/8
          y2[i] = yn;
          ybase[i] = yn;                                 // next step's stage-0 input
          float lo, hi; upk2(yn, lo, hi);
          int g0 = row0 + rb + 2*i;
          out[((size_t)g0*NT + step + 1)*DIMA + dd]     = lo;
          out[((size_t)(g0+1)*NT + step + 1)*DIMA + dd] = hi;
        }
      }
      __syncthreads();
    }
  }
}

extern "C" void kernel_launch(void* const* d_in, const int* in_sizes, int n_in,
                              void* d_out, int out_size)
{
  const float* fp = (const float*)d_in[0];   // first_point (3,2048,123)
  const float* ts = (const float*)d_in[1];   // time_steps (50)
  const float* W1 = (const float*)d_in[2];   // (256,128)
  const float* b1 = (const float*)d_in[3];   // (256)
  const float* W2 = (const float*)d_in[4];   // (128,256)
  const float* b2 = (const float*)d_in[5];   // (128)
  float* out = (float*)d_out;                // (3,2048,50,128)

  cudaFuncSetAttribute(ode_rk4_kernel,
                       cudaFuncAttributeMaxDynamicSharedMemorySize, SMEM_BYTES);
  ode_rk4_kernel<<<NBLK, NTHR, SMEM_BYTES>>>(fp, ts, W1, b1, W2, b2, out);
}

// round 5
// speedup vs baseline: 1.5135x; 1.5135x over previous
#include <cuda_runtime.h>
#include <math.h>

typedef unsigned long long ull;

#define TRAJ 3
#define BATCH 2048
#define NROW 6144
#define LAT 123
#define DIMA 128
#define HID 256
#define NT 50
#define NSTEP 49

#define NTHR 256
#define MROW 48
#define NBLK 128            // 6144 / 48, single wave on 148 SMs

// smem (in ull units): yin[24 pairs][128 d] | act[24 pairs][256 j] | ksm[3][12][256 tid]
#define YW DIMA
#define AW HID
#define ACT_OFF (24*YW)                 // 3072
#define KSM_OFF (ACT_OFF + 24*AW)       // 9216
#define SMEM_ULL (KSM_OFF + 36*NTHR)    // 18432
#define SMEM_BYTES (SMEM_ULL*8)         // 147456 B

// transposed weights (+2-chunk pad so prefetch never reads OOB)
__device__ float g_w1t[(DIMA+8)*HID];   // [d][j], j contiguous
__device__ float g_w2t[(HID+8)*DIMA];   // [j][d], d contiguous

// ---- packed f32x2 helpers ----
__device__ __forceinline__ ull pk2(float lo, float hi){
  ull r; asm("mov.b64 %0, {%1, %2};" : "=l"(r) : "f"(lo), "f"(hi)); return r;
}
__device__ __forceinline__ void upk2(ull v, float &lo, float &hi){
  asm("mov.b64 {%0, %1}, %2;" : "=f"(lo), "=f"(hi) : "l"(v));
}
__device__ __forceinline__ ull fma2_(ull a, ull b, ull c){
  ull d; asm("fma.rn.f32x2 %0, %1, %2, %3;" : "=l"(d) : "l"(a), "l"(b), "l"(c)); return d;
}
__device__ __forceinline__ ull add2_(ull a, ull b){
  ull d; asm("add.rn.f32x2 %0, %1, %2;" : "=l"(d) : "l"(a), "l"(b)); return d;
}
__device__ __forceinline__ ull dup2(float x){ return pk2(x,x); }

// tanh via exp: |err| ~1e-6 (2 MUFU). Keeps rel_err ~1e-6 overall.
__device__ __forceinline__ float fast_tanh(float x){
  float ax = fabsf(x);
  float e = __expf(-2.0f * ax);
  float r = __fdividef(1.0f - e, 1.0f + e);
  return copysignf(r, x);
}
__device__ __forceinline__ ull tanh2b(ull v, float b){
  float lo, hi; upk2(v, lo, hi);
  lo = fast_tanh(lo + b);
  hi = fast_tanh(hi + b);
  return pk2(lo, hi);
}

__global__ void transpose_kernel(const float* __restrict__ W1, const float* __restrict__ W2){
  int i = blockIdx.x*256 + threadIdx.x;        // 0..32767
  int d = i >> 8, j = i & 255;
  g_w1t[i] = W1[j*DIMA + d];                   // w1t[d][j]
  int j2 = i >> 7, d2 = i & 127;
  g_w2t[i] = W2[d2*HID + j2];                  // w2t[j][d]
}

__global__ __launch_bounds__(NTHR, 1)
void ode_kernel(const float* __restrict__ fp, const float* __restrict__ ts,
                const float* __restrict__ b1, const float* __restrict__ b2,
                float* __restrict__ out)
{
  extern __shared__ ull sm[];
  ull* yin = sm;                // [pair][d]  packed row-pairs
  ull* act = sm + ACT_OFF;      // [pair][j]
  ull* ksm = sm + KSM_OFF;      // [(kk*12 + dl*6 + p)*256 + tid]

  const int tid = threadIdx.x;
  const int g1  = tid & 63;     // feature group (P1: 4 j's; P2: 2 d's)
  const int rg  = tid >> 6;     // row group 0..3 (12 rows = 6 pairs)
  const int j0  = g1*4;
  const int d0  = g1*2;
  const int p0  = rg*6;
  const int grow0 = blockIdx.x*MROW + rg*12;   // global row of local pair p: grow0 + 2p

  const float bj0 = __ldg(b1+j0),   bj1 = __ldg(b1+j0+1);
  const float bj2 = __ldg(b1+j0+2), bj3 = __ldg(b1+j0+3);
  const float bd0f = __ldg(b2+d0),  bd1f = __ldg(b2+d0+1);
  const ull bd0 = dup2(bd0f), bd1 = dup2(bd1f);

  #define KIDX(kk,dl,p) ksm[(((kk)*12) + (dl)*6 + (p))*NTHR + tid]

  // ---- init: y0 = [first_point | 0(AUG)], write t=0 output ----
  ull y2[2][6];
  #pragma unroll
  for (int p=0; p<6; ++p){
    int g = grow0 + 2*p;
    #pragma unroll
    for (int dl=0; dl<2; ++dl){
      int d = d0 + dl;
      float v0 = (d < LAT) ? __ldg(fp + (size_t)g*LAT + d)     : 0.0f;
      float v1 = (d < LAT) ? __ldg(fp + (size_t)(g+1)*LAT + d) : 0.0f;
      y2[dl][p] = pk2(v0, v1);
    }
    ulonglong2 yy; yy.x = y2[0][p]; yy.y = y2[1][p];
    *(ulonglong2*)&yin[(p0+p)*YW + d0] = yy;
    float l0,h0,l1,h1; upk2(y2[0][p], l0, h0); upk2(y2[1][p], l1, h1);
    *(float2*)(out + ((size_t)g*NT)*DIMA + d0)     = make_float2(l0, l1);
    *(float2*)(out + ((size_t)(g+1)*NT)*DIMA + d0) = make_float2(h0, h1);
  }
  __syncthreads();

  #pragma unroll 1
  for (int step=0; step<NSTEP; ++step){
    const float t0 = __ldg(ts+step), t1 = __ldg(ts+step+1);
    const float h = t1 - t0;

    #pragma unroll 1
    for (int st=0; st<4; ++st){
      // ================= phase 1: act = tanh(yin @ W1^T + b1) =================
      ull acc[4][6];
      #pragma unroll
      for (int jj=0;jj<4;jj++)
        #pragma unroll
        for (int p=0;p<6;p++) acc[jj][p] = 0ull;

      {
        float4 wqA[4], wqB[4];
        #pragma unroll
        for (int i=0;i<4;i++){
          wqA[i] = __ldg((const float4*)&g_w1t[(size_t)(i)*HID + j0]);
          wqB[i] = __ldg((const float4*)&g_w1t[(size_t)(4+i)*HID + j0]);
        }
        auto p1_body = [&](int c, float4* wb){
          float4 cw[4];
          #pragma unroll
          for (int i=0;i<4;i++) cw[i] = wb[i];
          #pragma unroll
          for (int i=0;i<4;i++)
            wb[i] = __ldg((const float4*)&g_w1t[(size_t)(4*(c+2)+i)*HID + j0]);
          ull wp[16];
          #pragma unroll
          for (int i=0;i<4;i++){
            wp[i*4+0] = dup2(cw[i].x); wp[i*4+1] = dup2(cw[i].y);
            wp[i*4+2] = dup2(cw[i].z); wp[i*4+3] = dup2(cw[i].w);
          }
          #pragma unroll
          for (int p=0;p<6;p++){
            const ull* yb = &yin[(p0+p)*YW + 4*c];
            ulonglong2 ya = *(const ulonglong2*)yb;
            ulonglong2 yc = *(const ulonglong2*)(yb+2);
            ull yv[4] = {ya.x, ya.y, yc.x, yc.y};
            #pragma unroll
            for (int i=0;i<4;i++)
              #pragma unroll
              for (int jj=0;jj<4;jj++)
                acc[jj][p] = fma2_(wp[i*4+jj], yv[i], acc[jj][p]);
          }
        };
        #pragma unroll 1
        for (int cc=0; cc<32; cc+=2){
          p1_body(cc,   wqA);
          p1_body(cc+1, wqB);
        }
      }

      // epilogue: bias + tanh, store packed pairs into act
      #pragma unroll
      for (int p=0;p<6;p++){
        ull t0v = tanh2b(acc[0][p], bj0);
        ull t1v = tanh2b(acc[1][p], bj1);
        ull t2v = tanh2b(acc[2][p], bj2);
        ull t3v = tanh2b(acc[3][p], bj3);
        ulonglong2 s0; s0.x = t0v; s0.y = t1v;
        ulonglong2 s1; s1.x = t2v; s1.y = t3v;
        *(ulonglong2*)&act[(p0+p)*AW + j0]     = s0;
        *(ulonglong2*)&act[(p0+p)*AW + j0 + 2] = s1;
      }
      __syncthreads();

      // ================= phase 2: k = act @ W2^T + b2 =================
      ull a2[2][6];
      #pragma unroll
      for (int p=0;p<6;p++){ a2[0][p] = bd0; a2[1][p] = bd1; }

      {
        float2 vqA[4], vqB[4];
        #pragma unroll
        for (int i=0;i<4;i++){
          vqA[i] = __ldg((const float2*)&g_w2t[(size_t)(i)*DIMA + d0]);
          vqB[i] = __ldg((const float2*)&g_w2t[(size_t)(4+i)*DIMA + d0]);
        }
        auto p2_body = [&](int c, float2* wb){
          float2 cw[4];
          #pragma unroll
          for (int i=0;i<4;i++) cw[i] = wb[i];
          #pragma unroll
          for (int i=0;i<4;i++)
            wb[i] = __ldg((const float2*)&g_w2t[(size_t)(4*(c+2)+i)*DIMA + d0]);
          ull wp[8];
          #pragma unroll
          for (int i=0;i<4;i++){
            wp[i*2+0] = dup2(cw[i].x);
            wp[i*2+1] = dup2(cw[i].y);
          }
          #pragma unroll
          for (int p=0;p<6;p++){
            const ull* ab = &act[(p0+p)*AW + 4*c];
            ulonglong2 aa = *(const ulonglong2*)ab;
            ulonglong2 ac = *(const ulonglong2*)(ab+2);
            ull av[4] = {aa.x, aa.y, ac.x, ac.y};
            #pragma unroll
            for (int i=0;i<4;i++)
              #pragma unroll
              for (int dl=0;dl<2;dl++)
                a2[dl][p] = fma2_(wp[i*2+dl], av[i], a2[dl][p]);
          }
        };
        #pragma unroll 1
        for (int cc=0; cc<64; cc+=2){
          p2_body(cc,   vqA);
          p2_body(cc+1, vqB);
        }
      }

      // ================= RK4(3/8) stage update =================
      if (st == 0){
        const ull H3 = dup2(h*(1.0f/3.0f));
        #pragma unroll
        for (int p=0;p<6;p++){
          KIDX(0,0,p) = a2[0][p];
          KIDX(0,1,p) = a2[1][p];
          ulonglong2 s;
          s.x = fma2_(H3, a2[0][p], y2[0][p]);
          s.y = fma2_(H3, a2[1][p], y2[1][p]);
          *(ulonglong2*)&yin[(p0+p)*YW + d0] = s;
        }
      } else if (st == 1){
        const ull Hp  = dup2(h);
        const ull nH3 = dup2(-h*(1.0f/3.0f));
        #pragma unroll
        for (int p=0;p<6;p++){
          ulonglong2 s;
          #pragma unroll
          for (int dl=0;dl<2;dl++){
            KIDX(1,dl,p) = a2[dl][p];
            ull v = fma2_(Hp, a2[dl][p], y2[dl][p]);
            v = fma2_(nH3, KIDX(0,dl,p), v);
            if (dl==0) s.x = v; else s.y = v;
          }
          *(ulonglong2*)&yin[(p0+p)*YW + d0] = s;
        }
      } else if (st == 2){
        const ull Hp = dup2(h);
        const ull N1 = dup2(-1.0f);
        #pragma unroll
        for (int p=0;p<6;p++){
          ulonglong2 s;
          #pragma unroll
          for (int dl=0;dl<2;dl++){
            KIDX(2,dl,p) = a2[dl][p];
            ull t = fma2_(N1, KIDX(1,dl,p), KIDX(0,dl,p));   // k1 - k2
            t = add2_(t, a2[dl][p]);                         //   + k3
            ull v = fma2_(Hp, t, y2[dl][p]);
            if (dl==0) s.x = v; else s.y = v;
          }
          *(ulonglong2*)&yin[(p0+p)*YW + d0] = s;
        }
      } else {
        const ull TH = dup2(3.0f);
        const ull H8 = dup2(h*0.125f);
        #pragma unroll
        for (int p=0;p<6;p++){
          #pragma unroll
          for (int dl=0;dl<2;dl++){
            ull t = add2_(KIDX(0,dl,p), a2[dl][p]);          // k1 + k4
            ull u = add2_(KIDX(1,dl,p), KIDX(2,dl,p));       // k2 + k3
            t = fma2_(TH, u, t);                             // k1+3k2+3k3+k4
            y2[dl][p] = fma2_(H8, t, y2[dl][p]);
          }
          ulonglong2 s; s.x = y2[0][p]; s.y = y2[1][p];
          *(ulonglong2*)&yin[(p0+p)*YW + d0] = s;            // next step stage-0 input
          float l0,h0,l1,h1; upk2(y2[0][p], l0, h0); upk2(y2[1][p], l1, h1);
          int g = grow0 + 2*p;
          *(float2*)(out + ((size_t)g*NT + step+1)*DIMA + d0)     = make_float2(l0, l1);
          *(float2*)(out + ((size_t)(g+1)*NT + step+1)*DIMA + d0) = make_float2(h0, h1);
        }
      }
      __syncthreads();
    }
  }
  #undef KIDX
}

extern "C" void kernel_launch(void* const* d_in, const int* in_sizes, int n_in,
                              void* d_out, int out_size)
{
  const float* fp = (const float*)d_in[0];   // first_point (3,2048,123)
  const float* ts = (const float*)d_in[1];   // time_steps (50)
  const float* W1 = (const float*)d_in[2];   // (256,128)
  const float* b1 = (const float*)d_in[3];   // (256)
  const float* W2 = (const float*)d_in[4];   // (128,256)
  const float* b2 = (const float*)d_in[5];   // (128)
  float* out = (float*)d_out;                // (3,2048,50,128)

  transpose_kernel<<<128, 256>>>(W1, W2);

  cudaFuncSetAttribute(ode_kernel,
                       cudaFuncAttributeMaxDynamicSharedMemorySize, SMEM_BYTES);
  ode_kernel<<<NBLK, NTHR, SMEM_BYTES>>>(fp, ts, b1, b2, out);
}